// round 15
// baseline (speedup 1.0000x reference)
#include <cuda_runtime.h>
#include <cuda_fp16.h>
#include <cstdint>

// HyenaSE gated causal depthwise conv via banded-Toeplitz GEMM on
// mma.sync.m16n8k16 (fp16, base ISA; tcgen05 unsupported at sm_103 target).
// y[b,d,l] = q * sum_s (k*x)[b,d,l-s] * h[d%256][127-s]
//
// R15: R14 was L1-bound (90.5%) and 2/3 of mainloop wavefronts were A-band
// ldsm4 loads -- of data that is IDENTICAL across k-step reuse, channels,
// and warps. A fragments (9 ksteps x ah4+al4 = 72 regs) are now hoisted
// into registers ONCE per block and reused for all 4 half-channels:
// mainloop smem wf/warp-channel 108 -> 36. Occupancy raised to 6 blocks/SM
// (208KB smem, 48 warps). Else as R14: fp16 2-term split (A exact hi+lo,
// B rounded once; rel_err ~2e-4), cp.async staging of next half-channel
// under current MMA, direct scattered fragment epilogue.

typedef unsigned long long u64;

#define B_  2
#define D_  4096
#define L_  4096
#define G_  256
#define HL_ 128

static constexpr int THREADS = 256;
static constexpr int NIT = 4;                 // half-channels per block

static constexpr int APITCH = 304;            // Aband row pitch bytes
static constexpr int BPITCH = 528;            // B row pitch bytes
static constexpr int NSTG = 2176;             // staged floats per array

// smem byte offsets
static constexpr int SM_ABH   = 0;            // 16*304 = 4864
static constexpr int SM_ABL   = 4864;         // end 9728
static constexpr int SM_STG_X = 9728;         // 2176*4 = 8704 -> 18432
static constexpr int SM_STG_K = 18432;        // -> 27136
static constexpr int SM_B     = 27136;        // Bh only: 16*528 = 8448
static constexpr int SM_TOTAL = 35584;        // ~34.75KB -> 6 blocks/SM

__device__ __forceinline__ void ldsm4(uint32_t* r, uint32_t addr) {
    asm volatile("ldmatrix.sync.aligned.m8n8.x4.shared.b16 {%0,%1,%2,%3}, [%4];"
        : "=r"(r[0]), "=r"(r[1]), "=r"(r[2]), "=r"(r[3]) : "r"(addr));
}
__device__ __forceinline__ void ldsm2(uint32_t* r, uint32_t addr) {
    asm volatile("ldmatrix.sync.aligned.m8n8.x2.shared.b16 {%0,%1}, [%2];"
        : "=r"(r[0]), "=r"(r[1]) : "r"(addr));
}
__device__ __forceinline__ void mma16816(float* d, const uint32_t* a, const uint32_t* b) {
    asm volatile("mma.sync.aligned.m16n8k16.row.col.f32.f16.f16.f32 "
        "{%0,%1,%2,%3}, {%4,%5,%6,%7}, {%8,%9}, {%0,%1,%2,%3};"
        : "+f"(d[0]), "+f"(d[1]), "+f"(d[2]), "+f"(d[3])
        : "r"(a[0]), "r"(a[1]), "r"(a[2]), "r"(a[3]), "r"(b[0]), "r"(b[1]));
}
__device__ __forceinline__ void cp16(uint32_t daddr, const void* g) {
    asm volatile("cp.async.cg.shared.global [%0], [%1], 16;"
                 :: "r"(daddr), "l"(g));
}
__device__ __forceinline__ uint32_t pack_h2(float a, float b) {
    __half2 p = __floats2half2_rn(a, b);
    return *(uint32_t*)&p;
}

__global__ void __launch_bounds__(THREADS, 6)
hyena_mma_kernel(const float* __restrict__ x, const float* __restrict__ k,
                 const float* __restrict__ q, const float* __restrict__ h,
                 float* __restrict__ out)
{
    extern __shared__ __align__(16) char sm[];
    const uint32_t sbase = (uint32_t)__cvta_generic_to_shared(sm);
    const int tid = threadIdx.x, wid = tid >> 5, lid = tid & 31;
    const int g = blockIdx.x;
    const int half  = blockIdx.y & 1;
    const int b     = (blockIdx.y >> 1) & 1;
    const int chunk = blockIdx.y >> 2;           // 0..3: channels 4*chunk+i

    // ---- Toeplitz band: Aband[r][u] = h[g][u-r-1], u in [0,144).
    // Exact fp16 split: A = Ah + Al.
    {
        const float* hg = h + g * HL_;
        const int r = tid & 15;
        const int u0 = (tid >> 4) * 9;
        __half* abh = (__half*)(sm + SM_ABH + r * APITCH);
        __half* abl = (__half*)(sm + SM_ABL + r * APITCH);
        #pragma unroll
        for (int i = 0; i < 9; i++) {
            const int u = u0 + i;
            const int s = u - r - 1;
            float v = (s >= 0 && s < HL_) ? hg[s] : 0.f;
            __half vh = __float2half_rn(v);
            abh[u] = vh;
            abl[u] = __float2half_rn(v - __half2float(vh));
        }
    }

    auto chanRow = [&](int i) -> long {
        return ((long)b * D_ + g + 256 * (4 * chunk + i)) * L_;
    };

    // Stage xs/ks = raw floats at [chanRow + 2048*half - 128, +2176).
    auto stage = [&](int i) {
        const long base = chanRow(i) + 2048 * half - 128;
        #pragma unroll
        for (int v = tid; v < 2 * (NSTG / 4); v += THREADS) {  // 272 float4
            const int isK = (v >= NSTG / 4);
            const int vv  = isK ? v - NSTG / 4 : v;
            const uint32_t daddr = sbase + (isK ? SM_STG_K : SM_STG_X)
                                 + (uint32_t)vv * 16;
            if (half == 0 && vv < 32) {
                *(float4*)(sm + (isK ? SM_STG_K : SM_STG_X) + vv * 16)
                    = make_float4(0.f, 0.f, 0.f, 0.f);
            } else {
                const float* src = (isK ? k : x) + base + 4 * (long)vv;
                cp16(daddr, src);
            }
        }
        asm volatile("cp.async.commit_group;");
    };

    // Build Bh[n][j] = fp16(xs[128n+j]*ks[128n+j]) (n<16, j<256).
    const int bn = tid >> 4;           // 0..15
    const int bj = 4 * (tid & 15);     // 0..60
    auto buildB = [&]() {
        const float* xs = (const float*)(sm + SM_STG_X);
        const float* ks = (const float*)(sm + SM_STG_K);
        #pragma unroll
        for (int c = 0; c < 4; c++) {
            const int pos = 128 * bn + bj + 64 * c;
            float4 xv = *(const float4*)(xs + pos);
            float4 kv = *(const float4*)(ks + pos);
            uint2 pk = make_uint2(pack_h2(xv.x * kv.x, xv.y * kv.y),
                                  pack_h2(xv.z * kv.z, xv.w * kv.w));
            *(uint2*)(sm + SM_B + (uint32_t)bn * BPITCH
                      + (uint32_t)(bj + 64 * c) * 2) = pk;
        }
    };

    // ---- prologue
    stage(0);
    asm volatile("cp.async.wait_group 0;");
    __syncthreads();                   // staging + Aband visible
    buildB();

    // ---- hoist ALL A fragments to registers (channel/kstep-invariant)
    const int amat = lid >> 3, arow = lid & 7;
    const uint32_t aH = sbase + SM_ABH
        + (uint32_t)(((amat & 1) * 8 + arow) * APITCH + ((amat >> 1) * 8) * 2);
    uint32_t afh[9][4], afl[9][4];
    #pragma unroll
    for (int c = 0; c < 9; c++) {
        ldsm4(afh[c], aH + (uint32_t)(32 * c));
        ldsm4(afl[c], aH + (uint32_t)(SM_ABL - SM_ABH + 32 * c));
    }

    __syncthreads();                   // B visible; staging free
    stage(1);

    const uint32_t bbase = sbase + SM_B
        + (uint32_t)((lid & 7) * BPITCH + ((lid >> 3) & 1) * 16);

    // Fragment-direct output geometry
    const int m0 = 16 * wid + (lid >> 2);
    const int n0 = 2 * (lid & 3);

    #pragma unroll 1
    for (int i = 0; i < NIT; i++) {
        // -- MMA mainloop; warp w covers banded ksteps w..w+8
        float d[2][4];
        #pragma unroll
        for (int nc = 0; nc < 2; nc++)
            #pragma unroll
            for (int jj = 0; jj < 4; jj++) d[nc][jj] = 0.f;

        #pragma unroll
        for (int c = 0; c < 9; c++) {
            const uint32_t koff = 32u * (uint32_t)(wid + c);
            #pragma unroll
            for (int nc = 0; nc < 2; nc++) {
                uint32_t bh[2];
                ldsm2(bh, bbase + (uint32_t)(nc * 8 * BPITCH) + koff);
                mma16816(d[nc], afh[c], bh);
                mma16816(d[nc], afl[c], bh);
            }
        }

        // -- direct scattered q-gate + store: l = 2048*half + 128n + m
        {
            const long rowc = chanRow(i) + 2048 * half;
            float qv[8];
            #pragma unroll
            for (int nc = 0; nc < 2; nc++)
                #pragma unroll
                for (int jj = 0; jj < 4; jj++) {
                    const int n = 8 * nc + n0 + (jj & 1);
                    const int m = m0 + 8 * (jj >> 1);
                    qv[nc * 4 + jj] = q[rowc + 128 * n + m];
                }
            #pragma unroll
            for (int nc = 0; nc < 2; nc++)
                #pragma unroll
                for (int jj = 0; jj < 4; jj++) {
                    const int n = 8 * nc + n0 + (jj & 1);
                    const int m = m0 + 8 * (jj >> 1);
                    out[rowc + 128 * n + m] = qv[nc * 4 + jj] * d[nc][jj];
                }
        }

        // -- consume staged half-channel i+1; kick stage i+2
        if (i + 1 < NIT) {
            asm volatile("cp.async.wait_group 0;");
            __syncthreads();           // staging visible; B reads done
            buildB();
            __syncthreads();           // B visible; staging free
            if (i + 2 < NIT) stage(i + 2);
        }
    }
}

extern "C" void kernel_launch(void* const* d_in, const int* in_sizes, int n_in,
                              void* d_out, int out_size) {
    // metadata order: x, k, q, h  (all float32); output float32 (B,D,L)
    const float* x = (const float*)d_in[0];
    const float* k = (const float*)d_in[1];
    const float* q = (const float*)d_in[2];
    const float* h = (const float*)d_in[3];
    float* out = (float*)d_out;

    cudaFuncSetAttribute(hyena_mma_kernel,
                         cudaFuncAttributeMaxDynamicSharedMemorySize, SM_TOTAL);
    // grid.y: bit0 = L-half, bit1 = batch, bits2+ = 4-channel chunk
    dim3 grid(G_, B_ * 2 * 4);   // 256 x 16 = 4096 blocks
    hyena_mma_kernel<<<grid, THREADS, SM_TOTAL>>>(x, k, q, h, out);
}

// round 16
// speedup vs baseline: 5.4556x; 5.4556x over previous
#include <cuda_runtime.h>
#include <cuda_fp16.h>
#include <cstdint>

// HyenaSE gated causal depthwise conv via banded-Toeplitz GEMM on
// mma.sync.m16n8k16 (fp16, base ISA; tcgen05 unsupported at sm_103 target).
// y[b,d,l] = q * sum_s (k*x)[b,d,l-s] * h[d%256][127-s]
//
// R16: R15's register hoist spilled (launch_bounds reg cap 42 vs 117
// needed) -> 4.7x regression. Revert to R14 structure and instead cut the
// SECOND split term: both A and B rounded once to fp16. Independent
// rounding errors add in quadrature: rel_err ~ sqrt(2)*2.07e-4 ~ 3e-4,
// still 3.3x under 1e-3. Per kstep: 12->8 L1 wavefronts, 2->1 MMA.
// Smem 30KB. 5 blocks/SM (reg cap 51, occ 62.5%) -- one change at a time.
// Core: 16x144 Toeplitz band (fp16) shared by all warps; warp w covers
// banded ksteps w..w+8; cp.async staging of next half-channel under the
// current MMA; direct scattered fragment epilogue (full 32B sectors).

typedef unsigned long long u64;

#define B_  2
#define D_  4096
#define L_  4096
#define G_  256
#define HL_ 128

static constexpr int THREADS = 256;
static constexpr int NIT = 4;                 // half-channels per block

static constexpr int APITCH = 304;            // Aband row pitch bytes
static constexpr int BPITCH = 528;            // B row pitch bytes
static constexpr int NSTG = 2176;             // staged floats per array

// smem byte offsets
static constexpr int SM_ABH   = 0;            // 16*304 = 4864
static constexpr int SM_STG_X = 4864;         // 2176*4 = 8704 -> 13568
static constexpr int SM_STG_K = 13568;        // -> 22272
static constexpr int SM_B     = 22272;        // Bh: 16*528 = 8448
static constexpr int SM_TOTAL = 30720;        // 30KB -> 5 blocks/SM fits

__device__ __forceinline__ void ldsm4(uint32_t* r, uint32_t addr) {
    asm volatile("ldmatrix.sync.aligned.m8n8.x4.shared.b16 {%0,%1,%2,%3}, [%4];"
        : "=r"(r[0]), "=r"(r[1]), "=r"(r[2]), "=r"(r[3]) : "r"(addr));
}
__device__ __forceinline__ void ldsm2(uint32_t* r, uint32_t addr) {
    asm volatile("ldmatrix.sync.aligned.m8n8.x2.shared.b16 {%0,%1}, [%2];"
        : "=r"(r[0]), "=r"(r[1]) : "r"(addr));
}
__device__ __forceinline__ void mma16816(float* d, const uint32_t* a, const uint32_t* b) {
    asm volatile("mma.sync.aligned.m16n8k16.row.col.f32.f16.f16.f32 "
        "{%0,%1,%2,%3}, {%4,%5,%6,%7}, {%8,%9}, {%0,%1,%2,%3};"
        : "+f"(d[0]), "+f"(d[1]), "+f"(d[2]), "+f"(d[3])
        : "r"(a[0]), "r"(a[1]), "r"(a[2]), "r"(a[3]), "r"(b[0]), "r"(b[1]));
}
__device__ __forceinline__ void cp16(uint32_t daddr, const void* g) {
    asm volatile("cp.async.cg.shared.global [%0], [%1], 16;"
                 :: "r"(daddr), "l"(g));
}
__device__ __forceinline__ uint32_t pack_h2(float a, float b) {
    __half2 p = __floats2half2_rn(a, b);
    return *(uint32_t*)&p;
}

__global__ void __launch_bounds__(THREADS, 5)
hyena_mma_kernel(const float* __restrict__ x, const float* __restrict__ k,
                 const float* __restrict__ q, const float* __restrict__ h,
                 float* __restrict__ out)
{
    extern __shared__ __align__(16) char sm[];
    const uint32_t sbase = (uint32_t)__cvta_generic_to_shared(sm);
    const int tid = threadIdx.x, wid = tid >> 5, lid = tid & 31;
    const int g = blockIdx.x;
    const int half  = blockIdx.y & 1;
    const int b     = (blockIdx.y >> 1) & 1;
    const int chunk = blockIdx.y >> 2;           // 0..3: channels 4*chunk+i

    // ---- Toeplitz band: Aband[r][u] = fp16(h[g][u-r-1]), u in [0,144)
    {
        const float* hg = h + g * HL_;
        const int r = tid & 15;
        const int u0 = (tid >> 4) * 9;
        __half* abh = (__half*)(sm + SM_ABH + r * APITCH);
        #pragma unroll
        for (int i = 0; i < 9; i++) {
            const int u = u0 + i;
            const int s = u - r - 1;
            float v = (s >= 0 && s < HL_) ? hg[s] : 0.f;
            abh[u] = __float2half_rn(v);
        }
    }

    auto chanRow = [&](int i) -> long {
        return ((long)b * D_ + g + 256 * (4 * chunk + i)) * L_;
    };

    // Stage xs/ks = raw floats at [chanRow + 2048*half - 128, +2176).
    // half==0: first 128 floats are causal zeros.
    auto stage = [&](int i) {
        const long base = chanRow(i) + 2048 * half - 128;
        #pragma unroll
        for (int v = tid; v < 2 * (NSTG / 4); v += THREADS) {  // 272 float4
            const int isK = (v >= NSTG / 4);
            const int vv  = isK ? v - NSTG / 4 : v;
            const uint32_t daddr = sbase + (isK ? SM_STG_K : SM_STG_X)
                                 + (uint32_t)vv * 16;
            if (half == 0 && vv < 32) {
                *(float4*)(sm + (isK ? SM_STG_K : SM_STG_X) + vv * 16)
                    = make_float4(0.f, 0.f, 0.f, 0.f);
            } else {
                const float* src = (isK ? k : x) + base + 4 * (long)vv;
                cp16(daddr, src);
            }
        }
        asm volatile("cp.async.commit_group;");
    };

    // Build Bh[n][j] = fp16(xs[128n+j]*ks[128n+j]) (n<16, j<256).
    const int bn = tid >> 4;           // 0..15
    const int bj = 4 * (tid & 15);     // 0..60
    auto buildB = [&]() {
        const float* xs = (const float*)(sm + SM_STG_X);
        const float* ks = (const float*)(sm + SM_STG_K);
        #pragma unroll
        for (int c = 0; c < 4; c++) {
            const int pos = 128 * bn + bj + 64 * c;
            float4 xv = *(const float4*)(xs + pos);
            float4 kv = *(const float4*)(ks + pos);
            uint2 pk = make_uint2(pack_h2(xv.x * kv.x, xv.y * kv.y),
                                  pack_h2(xv.z * kv.z, xv.w * kv.w));
            *(uint2*)(sm + SM_B + (uint32_t)bn * BPITCH
                      + (uint32_t)(bj + 64 * c) * 2) = pk;
        }
    };

    // ---- prologue
    stage(0);
    asm volatile("cp.async.wait_group 0;");
    __syncthreads();                   // staging + Aband visible
    buildB();
    __syncthreads();                   // B visible; staging free
    stage(1);

    // ldmatrix lane bases
    const int amat = lid >> 3, arow = lid & 7;
    const uint32_t aH = sbase + SM_ABH
        + (uint32_t)(((amat & 1) * 8 + arow) * APITCH + ((amat >> 1) * 8) * 2);
    const uint32_t bbase = sbase + SM_B
        + (uint32_t)((lid & 7) * BPITCH + ((lid >> 3) & 1) * 16);

    // Fragment-direct output geometry
    const int m0 = 16 * wid + (lid >> 2);
    const int n0 = 2 * (lid & 3);

    #pragma unroll 1
    for (int i = 0; i < NIT; i++) {
        // -- MMA mainloop; warp w covers banded ksteps w..w+8
        float d[2][4];
        #pragma unroll
        for (int nc = 0; nc < 2; nc++)
            #pragma unroll
            for (int jj = 0; jj < 4; jj++) d[nc][jj] = 0.f;

        #pragma unroll 1
        for (int c = 0; c < 9; c++) {
            uint32_t ah[4];
            ldsm4(ah, aH + (uint32_t)(32 * c));
            const uint32_t koff = 32u * (uint32_t)(wid + c);
            #pragma unroll
            for (int nc = 0; nc < 2; nc++) {
                uint32_t bh[2];
                ldsm2(bh, bbase + (uint32_t)(nc * 8 * BPITCH) + koff);
                mma16816(d[nc], ah, bh);
            }
        }

        // -- direct scattered q-gate + store: l = 2048*half + 128n + m
        {
            const long rowc = chanRow(i) + 2048 * half;
            float qv[8];
            #pragma unroll
            for (int nc = 0; nc < 2; nc++)
                #pragma unroll
                for (int jj = 0; jj < 4; jj++) {
                    const int n = 8 * nc + n0 + (jj & 1);
                    const int m = m0 + 8 * (jj >> 1);
                    qv[nc * 4 + jj] = q[rowc + 128 * n + m];
                }
            #pragma unroll
            for (int nc = 0; nc < 2; nc++)
                #pragma unroll
                for (int jj = 0; jj < 4; jj++) {
                    const int n = 8 * nc + n0 + (jj & 1);
                    const int m = m0 + 8 * (jj >> 1);
                    out[rowc + 128 * n + m] = qv[nc * 4 + jj] * d[nc][jj];
                }
        }

        // -- consume staged half-channel i+1; kick stage i+2
        if (i + 1 < NIT) {
            asm volatile("cp.async.wait_group 0;");
            __syncthreads();           // staging visible; B reads done
            buildB();
            __syncthreads();           // B visible; staging free
            if (i + 2 < NIT) stage(i + 2);
        }
    }
}

extern "C" void kernel_launch(void* const* d_in, const int* in_sizes, int n_in,
                              void* d_out, int out_size) {
    // metadata order: x, k, q, h  (all float32); output float32 (B,D,L)
    const float* x = (const float*)d_in[0];
    const float* k = (const float*)d_in[1];
    const float* q = (const float*)d_in[2];
    const float* h = (const float*)d_in[3];
    float* out = (float*)d_out;

    cudaFuncSetAttribute(hyena_mma_kernel,
                         cudaFuncAttributeMaxDynamicSharedMemorySize, SM_TOTAL);
    // grid.y: bit0 = L-half, bit1 = batch, bits2+ = 4-channel chunk
    dim3 grid(G_, B_ * 2 * 4);   // 256 x 16 = 4096 blocks
    hyena_mma_kernel<<<grid, THREADS, SM_TOTAL>>>(x, k, q, h, out);
}

// round 17
// speedup vs baseline: 5.5658x; 1.0202x over previous
#include <cuda_runtime.h>
#include <cuda_fp16.h>
#include <cstdint>

// HyenaSE gated causal depthwise conv via banded-Toeplitz GEMM on
// mma.sync.m16n8k16 (fp16, base ISA; tcgen05 unsupported at sm_103 target).
// y[b,d,l] = q * sum_s (k*x)[b,d,l-s] * h[d%256][127-s]
//
// R17: R16 still L1-bound (86%) and the line-level wf audit showed the
// scattered fragment epilogue costs 4 wavefronts per 128B (4 lines per
// STG.32/LDG.32 instr) ~= the whole MMA mainloop. Epilogue now goes
// through an 8.4KB padded smem transpose: conflict-free STS.32 frag
// scatter (1 wf/instr), then fully coalesced LDS.128 + q LDG.128 +
// out STG.128. Still 5 blocks/SM (39.2KB smem). Also merged the two B
// ldsm2 into one ldsm4 (same wf, half the instructions).
// Core: fp16 single-rounding A and B (rel_err ~2.9e-4), 16x144 Toeplitz
// band shared by all warps, banded ksteps w..w+8 per warp, cp.async
// staging of next half-channel under current MMA.

typedef unsigned long long u64;

#define B_  2
#define D_  4096
#define L_  4096
#define G_  256
#define HL_ 128

static constexpr int THREADS = 256;
static constexpr int NIT = 4;                 // half-channels per block

static constexpr int APITCH = 304;            // Aband row pitch bytes
static constexpr int BPITCH = 528;            // B row pitch bytes
static constexpr int NSTG = 2176;             // staged floats per array
static constexpr int EPI_PITCH = 132;         // floats per epi row (16 rows)

// smem byte offsets
static constexpr int SM_ABH   = 0;            // 16*304 = 4864
static constexpr int SM_STG_X = 4864;         // 8704 -> 13568
static constexpr int SM_STG_K = 13568;        // -> 22272
static constexpr int SM_B     = 22272;        // Bh: 16*528 = 8448 -> 30720
static constexpr int SM_EPI   = 30720;        // 16*132*4 = 8448
static constexpr int SM_TOTAL = 39168;        // 38.25KB -> 5 blocks/SM

__device__ __forceinline__ void ldsm4(uint32_t* r, uint32_t addr) {
    asm volatile("ldmatrix.sync.aligned.m8n8.x4.shared.b16 {%0,%1,%2,%3}, [%4];"
        : "=r"(r[0]), "=r"(r[1]), "=r"(r[2]), "=r"(r[3]) : "r"(addr));
}
__device__ __forceinline__ void mma16816(float* d, const uint32_t* a, const uint32_t* b) {
    asm volatile("mma.sync.aligned.m16n8k16.row.col.f32.f16.f16.f32 "
        "{%0,%1,%2,%3}, {%4,%5,%6,%7}, {%8,%9}, {%0,%1,%2,%3};"
        : "+f"(d[0]), "+f"(d[1]), "+f"(d[2]), "+f"(d[3])
        : "r"(a[0]), "r"(a[1]), "r"(a[2]), "r"(a[3]), "r"(b[0]), "r"(b[1]));
}
__device__ __forceinline__ void cp16(uint32_t daddr, const void* g) {
    asm volatile("cp.async.cg.shared.global [%0], [%1], 16;"
                 :: "r"(daddr), "l"(g));
}
__device__ __forceinline__ uint32_t pack_h2(float a, float b) {
    __half2 p = __floats2half2_rn(a, b);
    return *(uint32_t*)&p;
}

__global__ void __launch_bounds__(THREADS, 5)
hyena_mma_kernel(const float* __restrict__ x, const float* __restrict__ k,
                 const float* __restrict__ q, const float* __restrict__ h,
                 float* __restrict__ out)
{
    extern __shared__ __align__(16) char sm[];
    const uint32_t sbase = (uint32_t)__cvta_generic_to_shared(sm);
    const int tid = threadIdx.x, wid = tid >> 5, lid = tid & 31;
    const int g = blockIdx.x;
    const int half  = blockIdx.y & 1;
    const int b     = (blockIdx.y >> 1) & 1;
    const int chunk = blockIdx.y >> 2;           // 0..3: channels 4*chunk+i

    // ---- Toeplitz band: Aband[r][u] = fp16(h[g][u-r-1]), u in [0,144)
    {
        const float* hg = h + g * HL_;
        const int r = tid & 15;
        const int u0 = (tid >> 4) * 9;
        __half* abh = (__half*)(sm + SM_ABH + r * APITCH);
        #pragma unroll
        for (int i = 0; i < 9; i++) {
            const int u = u0 + i;
            const int s = u - r - 1;
            float v = (s >= 0 && s < HL_) ? hg[s] : 0.f;
            abh[u] = __float2half_rn(v);
        }
    }

    auto chanRow = [&](int i) -> long {
        return ((long)b * D_ + g + 256 * (4 * chunk + i)) * L_;
    };

    // Stage xs/ks = raw floats at [chanRow + 2048*half - 128, +2176).
    auto stage = [&](int i) {
        const long base = chanRow(i) + 2048 * half - 128;
        #pragma unroll
        for (int v = tid; v < 2 * (NSTG / 4); v += THREADS) {  // 272 float4
            const int isK = (v >= NSTG / 4);
            const int vv  = isK ? v - NSTG / 4 : v;
            const uint32_t daddr = sbase + (isK ? SM_STG_K : SM_STG_X)
                                 + (uint32_t)vv * 16;
            if (half == 0 && vv < 32) {
                *(float4*)(sm + (isK ? SM_STG_K : SM_STG_X) + vv * 16)
                    = make_float4(0.f, 0.f, 0.f, 0.f);
            } else {
                const float* src = (isK ? k : x) + base + 4 * (long)vv;
                cp16(daddr, src);
            }
        }
        asm volatile("cp.async.commit_group;");
    };

    // Build Bh[n][j] = fp16(xs[128n+j]*ks[128n+j]) (n<16, j<256).
    const int bn = tid >> 4;           // 0..15
    const int bj = 4 * (tid & 15);     // 0..60
    auto buildB = [&]() {
        const float* xs = (const float*)(sm + SM_STG_X);
        const float* ks = (const float*)(sm + SM_STG_K);
        #pragma unroll
        for (int c = 0; c < 4; c++) {
            const int pos = 128 * bn + bj + 64 * c;
            float4 xv = *(const float4*)(xs + pos);
            float4 kv = *(const float4*)(ks + pos);
            uint2 pk = make_uint2(pack_h2(xv.x * kv.x, xv.y * kv.y),
                                  pack_h2(xv.z * kv.z, xv.w * kv.w));
            *(uint2*)(sm + SM_B + (uint32_t)bn * BPITCH
                      + (uint32_t)(bj + 64 * c) * 2) = pk;
        }
    };

    // ---- prologue
    stage(0);
    asm volatile("cp.async.wait_group 0;");
    __syncthreads();                   // staging + Aband visible
    buildB();
    __syncthreads();                   // B visible; staging free
    stage(1);

    // ldmatrix lane bases
    const int amat = lid >> 3, arow = lid & 7;
    const uint32_t aH = sbase + SM_ABH
        + (uint32_t)(((amat & 1) * 8 + arow) * APITCH + ((amat >> 1) * 8) * 2);
    // merged B ldsm4: lanes 0-7 n0-7|k0-7, 8-15 n0-7|k8-15,
    //                 16-23 n8-15|k0-7, 24-31 n8-15|k8-15
    const uint32_t bbase = sbase + SM_B
        + (uint32_t)((lid & 7) * BPITCH + ((lid >> 3) & 1) * 16
                     + (lid >> 4) * 8 * BPITCH);

    // frag scatter geometry
    const int m0 = 16 * wid + (lid >> 2);
    const int n0 = 2 * (lid & 3);
    // epi read geometry: row n = tid>>4, cols ms..ms+7
    const int en = tid >> 4;
    const int ems = 8 * (tid & 15);
    float* epi = (float*)(sm + SM_EPI);

    #pragma unroll 1
    for (int i = 0; i < NIT; i++) {
        // -- MMA mainloop; warp w covers banded ksteps w..w+8
        float d[2][4];
        #pragma unroll
        for (int nc = 0; nc < 2; nc++)
            #pragma unroll
            for (int jj = 0; jj < 4; jj++) d[nc][jj] = 0.f;

        #pragma unroll 1
        for (int c = 0; c < 9; c++) {
            uint32_t ah[4], bf[4];
            ldsm4(ah, aH + (uint32_t)(32 * c));
            ldsm4(bf, bbase + 32u * (uint32_t)(wid + c));
            mma16816(d[0], ah, bf);       // nc=0: frag {bf[0],bf[1]}
            mma16816(d[1], ah, bf + 2);   // nc=1: frag {bf[2],bf[3]}
        }

        // -- frag scatter to epi (conflict-free: banks 8a+b distinct)
        #pragma unroll
        for (int nc = 0; nc < 2; nc++)
            #pragma unroll
            for (int jj = 0; jj < 4; jj++) {
                const int n = 8 * nc + n0 + (jj & 1);
                const int m = m0 + 8 * (jj >> 1);
                epi[n * EPI_PITCH + m] = d[nc][jj];
            }
        __syncthreads();                   // frags visible

        // -- coalesced epilogue: l = 2048*half + 128*en + ems + j
        {
            const long rowl = chanRow(i) + 2048 * half + 128 * en + ems;
            const float* er = epi + en * EPI_PITCH + ems;
            #pragma unroll
            for (int v = 0; v < 2; v++) {
                float4 y  = *(const float4*)(er + 4 * v);
                float4 qv = *(const float4*)(q + rowl + 4 * v);
                *(float4*)(out + rowl + 4 * v) =
                    make_float4(qv.x * y.x, qv.y * y.y, qv.z * y.z, qv.w * y.w);
            }
        }

        // -- consume staged half-channel i+1; kick stage i+2
        if (i + 1 < NIT) {
            asm volatile("cp.async.wait_group 0;");
            __syncthreads();           // staging visible; B + epi reads done
            buildB();
            __syncthreads();           // B visible; staging + epi free
            if (i + 2 < NIT) stage(i + 2);
        }
    }
}

extern "C" void kernel_launch(void* const* d_in, const int* in_sizes, int n_in,
                              void* d_out, int out_size) {
    // metadata order: x, k, q, h  (all float32); output float32 (B,D,L)
    const float* x = (const float*)d_in[0];
    const float* k = (const float*)d_in[1];
    const float* q = (const float*)d_in[2];
    const float* h = (const float*)d_in[3];
    float* out = (float*)d_out;

    cudaFuncSetAttribute(hyena_mma_kernel,
                         cudaFuncAttributeMaxDynamicSharedMemorySize, SM_TOTAL);
    // grid.y: bit0 = L-half, bit1 = batch, bits2+ = 4-channel chunk
    dim3 grid(G_, B_ * 2 * 4);   // 256 x 16 = 4096 blocks
    hyena_mma_kernel<<<grid, THREADS, SM_TOTAL>>>(x, k, q, h, out);
}